// round 5
// baseline (speedup 1.0000x reference)
#include <cuda_runtime.h>
#include <cstdint>
#include <math.h>

#define NMAX 50176
#define EMAX 1700000
#define NEG 0.2f
#define FULL 0xffffffffu

// ---------------- device scratch (static; no allocation) ----------------
__device__ float g_h1[(size_t)NMAX * 48];
__device__ float g_h2[(size_t)NMAX * 60];
__device__ float g_h3[NMAX];
__device__ float g_as[NMAX];    // layer-1 alphas, then reused for layer-3 alphas
__device__ float g_ad[NMAX];
__device__ float g_asB[NMAX];   // layer-2 alphas
__device__ float g_adB[NMAX];
__device__ float g_elog[EMAX];  // cached edge logits
__device__ int   g_cnt[NMAX + 1];
__device__ int   g_ro[NMAX + 1];
__device__ int   g_nxt[NMAX];
__device__ int   g_csrc[EMAX];
__device__ int   g_bsum[64];
__device__ int   g_boff[64];
__device__ int   g_is64;

__device__ __forceinline__ float lrelu(float x) { return x > 0.f ? x : NEG * x; }

// ---------------- edge-index dtype detection ----------------
__global__ void detect_k(const void* ei) {
    int lane = threadIdx.x;
    const int* p = (const int*)ei;
    int v = p[2 * lane + 1];
    unsigned b = __ballot_sync(FULL, v == 0);
    if (lane == 0) g_is64 = (b == FULL) ? 1 : 0;
}

__device__ __forceinline__ int edge_val(const void* ei, int idx) {
    if (g_is64) return (int)((const long long*)ei)[idx];
    return ((const int*)ei)[idx];
}

// ---------------- CSR build ----------------
__global__ void zero_k(int n) {
    int i = blockIdx.x * blockDim.x + threadIdx.x;
    if (i < n) g_cnt[i] = 0;
}

__global__ void hist_k(const void* ei, int E) {
    int e = blockIdx.x * blockDim.x + threadIdx.x;
    if (e < E) {
        int d = edge_val(ei, E + e);
        atomicAdd(&g_cnt[d], 1);
    }
}

// multi-block exclusive scan of g_cnt[0..N) -> g_ro ; 1024 elems/block
__global__ __launch_bounds__(256) void scanA_k(int N) {
    __shared__ int wsum[8];
    int tid = threadIdx.x, lane = tid & 31, wid = tid >> 5;
    int base = blockIdx.x * 1024 + tid * 4;
    int v[4];
    #pragma unroll
    for (int k = 0; k < 4; k++) v[k] = (base + k < N) ? g_cnt[base + k] : 0;
    int s4 = v[0] + v[1] + v[2] + v[3];
    int x = s4;
    #pragma unroll
    for (int o = 1; o < 32; o <<= 1) {
        int t = __shfl_up_sync(FULL, x, o);
        if (lane >= o) x += t;
    }
    if (lane == 31) wsum[wid] = x;
    __syncthreads();
    if (wid == 0 && lane < 8) {
        int w = wsum[lane];
        #pragma unroll
        for (int o = 1; o < 8; o <<= 1) {
            int t = __shfl_up_sync(0xffu, w, o);
            if (lane >= o) w += t;
        }
        wsum[lane] = w;
    }
    __syncthreads();
    int excl = (wid ? wsum[wid - 1] : 0) + x - s4;
    int run = excl;
    #pragma unroll
    for (int k = 0; k < 4; k++) {
        if (base + k < N) g_ro[base + k] = run;
        run += v[k];
    }
    if (tid == 255) g_bsum[blockIdx.x] = wsum[7];
}

__global__ void scanB_k(int nb, int N) {
    int tid = threadIdx.x;  // 64 threads
    int lane = tid & 31, wid = tid >> 5;
    __shared__ int w0tot;
    int v = (tid < nb) ? g_bsum[tid] : 0;
    int x = v;
    #pragma unroll
    for (int o = 1; o < 32; o <<= 1) {
        int t = __shfl_up_sync(FULL, x, o);
        if (lane >= o) x += t;
    }
    if (wid == 0 && lane == 31) w0tot = x;
    __syncthreads();
    if (wid == 1) x += w0tot;
    g_boff[tid] = x - v;
    if (tid == 63) g_ro[N] = x;
}

__global__ __launch_bounds__(256) void scanC_k(int N) {
    int base = blockIdx.x * 1024 + threadIdx.x * 4;
    int off = g_boff[blockIdx.x];
    #pragma unroll
    for (int k = 0; k < 4; k++) {
        int i = base + k;
        if (i < N) {
            int r = g_ro[i] + off;
            g_ro[i] = r;
            g_nxt[i] = r;
        }
    }
}

__global__ void scat_k(const void* ei, int E) {
    int e = blockIdx.x * blockDim.x + threadIdx.x;
    if (e < E) {
        int s = edge_val(ei, e);
        int d = edge_val(ei, E + e);
        int p = atomicAdd(&g_nxt[d], 1);
        g_csrc[p] = s;
    }
}

// ---------------- GEMM layer 1: [N,256] x [256,48] -> g_h1 ; fused alpha ----------------
__global__ __launch_bounds__(256) void gemm1_k(const float* __restrict__ X,
                                               const float* __restrict__ W,
                                               const float* __restrict__ av_s,
                                               const float* __restrict__ av_d, int N) {
    __shared__ float sX[64][68];
    __shared__ float sW[64][48];
    int tid = threadIdx.x;
    int tx = tid & 15, ty = tid >> 4;
    int row0 = blockIdx.x * 64;
    float acc[4][3];
    #pragma unroll
    for (int i = 0; i < 4; i++)
        #pragma unroll
        for (int j = 0; j < 3; j++) acc[i][j] = 0.f;

    for (int k0 = 0; k0 < 256; k0 += 64) {
        for (int i = tid; i < 64 * 16; i += 256) {
            int r = i >> 4; int kq = (i & 15) * 4;
            int gr = row0 + r;
            float4 v = (gr < N) ? *(const float4*)&X[(size_t)gr * 256 + k0 + kq]
                                : make_float4(0.f, 0.f, 0.f, 0.f);
            *(float4*)&sX[r][kq] = v;
        }
        for (int i = tid; i < 64 * 12; i += 256) {
            int r = i / 12; int cq = (i % 12) * 4;
            float4 v = *(const float4*)&W[(size_t)(k0 + r) * 48 + cq];
            *(float4*)&sW[r][cq] = v;
        }
        __syncthreads();
        #pragma unroll 16
        for (int k = 0; k < 64; k++) {
            float a0 = sX[ty * 4 + 0][k], a1 = sX[ty * 4 + 1][k];
            float a2 = sX[ty * 4 + 2][k], a3 = sX[ty * 4 + 3][k];
            float w0 = sW[k][tx * 3 + 0], w1 = sW[k][tx * 3 + 1], w2 = sW[k][tx * 3 + 2];
            acc[0][0] += a0 * w0; acc[0][1] += a0 * w1; acc[0][2] += a0 * w2;
            acc[1][0] += a1 * w0; acc[1][1] += a1 * w1; acc[1][2] += a1 * w2;
            acc[2][0] += a2 * w0; acc[2][1] += a2 * w1; acc[2][2] += a2 * w2;
            acc[3][0] += a3 * w0; acc[3][1] += a3 * w1; acc[3][2] += a3 * w2;
        }
        __syncthreads();
    }
    #pragma unroll
    for (int i = 0; i < 4; i++) {
        int gr = row0 + ty * 4 + i;
        if (gr < N) {
            #pragma unroll
            for (int j = 0; j < 3; j++)
                g_h1[(size_t)gr * 48 + tx * 3 + j] = acc[i][j];
        }
    }
    // fused alpha: reduce over 16 threads of the same row group
    float a_s[3], a_d[3];
    #pragma unroll
    for (int j = 0; j < 3; j++) { a_s[j] = av_s[tx * 3 + j]; a_d[j] = av_d[tx * 3 + j]; }
    #pragma unroll
    for (int i = 0; i < 4; i++) {
        float ps = acc[i][0] * a_s[0] + acc[i][1] * a_s[1] + acc[i][2] * a_s[2];
        float pd = acc[i][0] * a_d[0] + acc[i][1] * a_d[1] + acc[i][2] * a_d[2];
        #pragma unroll
        for (int o = 8; o; o >>= 1) {
            ps += __shfl_down_sync(FULL, ps, o, 16);
            pd += __shfl_down_sync(FULL, pd, o, 16);
        }
        if (tx == 0) {
            int gr = row0 + ty * 4 + i;
            if (gr < N) { g_as[gr] = ps; g_ad[gr] = pd; }
        }
    }
}

// ---------------- fused segment softmax + aggregation (warp per node) ----------------
// LAYER==1: reads g_h1 + alphas(g_as/g_ad); epilogue computes out1 (relu), then
//           gemm2 (via smem W2^T broadcast) -> g_h2, and layer-2 alphas -> g_asB/adB.
// LAYER==2: reads g_h2 + alphas(g_asB/adB); epilogue computes out2 (relu), then
//           h3 = out2 @ W3 -> g_h3, and layer-3 alphas -> g_as/g_ad.
template <int LAYER>
__global__ __launch_bounds__(256) void agg_k(const float* __restrict__ bias,
                                             const float* __restrict__ Wnext,
                                             const float* __restrict__ asn,
                                             const float* __restrict__ adn_v, int N) {
    constexpr int F = (LAYER == 1) ? 48 : 60;
    constexpr int FV = F / 4;
    const float* h = (LAYER == 1) ? g_h1 : g_h2;
    const float* As = (LAYER == 1) ? g_as : g_asB;
    const float* Ad = (LAYER == 1) ? g_ad : g_adB;

    __shared__ float sW2t[60][52];  // used by LAYER==1 only (W2 transposed)
    __shared__ float sAs[60], sAd[60];

    int tid = threadIdx.x;
    if (LAYER == 1) {
        for (int i = tid; i < 48 * 60; i += 256) {
            int k = i / 60, c = i % 60;
            sW2t[c][k] = Wnext[i];
        }
        for (int i = tid; i < 60; i += 256) { sAs[i] = asn[i]; sAd[i] = adn_v[i]; }
        __syncthreads();
    }

    int n = (blockIdx.x * blockDim.x + tid) >> 5;
    int lane = tid & 31;
    if (n >= N) return;
    int beg = g_ro[n], end = g_ro[n + 1];
    float adn = Ad[n];
    float lself = lrelu(As[n] + adn);
    float m = lself;
    for (int j = beg + lane; j < end; j += 32) {
        float l = lrelu(As[g_csrc[j]] + adn);
        g_elog[j] = l;
        m = fmaxf(m, l);
    }
    #pragma unroll
    for (int o = 16; o; o >>= 1) m = fmaxf(m, __shfl_xor_sync(FULL, m, o));

    int half = lane >> 4;
    int hl = lane & 15;
    const bool act = hl < FV;
    float4 acc = make_float4(0.f, 0.f, 0.f, 0.f);
    float Sp = 0.f;
    for (int j0 = beg; j0 < end; j0 += 32) {
        int j = j0 + lane;
        int s = 0; float e = 0.f;
        if (j < end) {
            s = g_csrc[j];
            e = __expf(g_elog[j] - m);
            Sp += e;
        }
        int cnt = min(32, end - j0);
        int jj = 0;
        for (; jj + 4 <= cnt; jj += 4) {
            int i0 = jj + half, i1 = jj + 2 + half;
            float e0 = __shfl_sync(FULL, e, i0);
            int s0 = __shfl_sync(FULL, s, i0);
            float e1 = __shfl_sync(FULL, e, i1);
            int s1 = __shfl_sync(FULL, s, i1);
            if (act) {
                float4 h0 = *(const float4*)(h + (size_t)s0 * F + hl * 4);
                float4 h1 = *(const float4*)(h + (size_t)s1 * F + hl * 4);
                acc.x += e0 * h0.x; acc.y += e0 * h0.y;
                acc.z += e0 * h0.z; acc.w += e0 * h0.w;
                acc.x += e1 * h1.x; acc.y += e1 * h1.y;
                acc.z += e1 * h1.z; acc.w += e1 * h1.w;
            }
        }
        for (; jj < cnt; jj += 2) {
            int idx = jj + half;
            float ee = __shfl_sync(FULL, e, idx);
            int ss = __shfl_sync(FULL, s, idx);
            if (act && idx < cnt) {
                float4 hv = *(const float4*)(h + (size_t)ss * F + hl * 4);
                acc.x += ee * hv.x; acc.y += ee * hv.y;
                acc.z += ee * hv.z; acc.w += ee * hv.w;
            }
        }
    }
    // combine halves
    acc.x += __shfl_down_sync(FULL, acc.x, 16);
    acc.y += __shfl_down_sync(FULL, acc.y, 16);
    acc.z += __shfl_down_sync(FULL, acc.z, 16);
    acc.w += __shfl_down_sync(FULL, acc.w, 16);

    float es = __expf(lself - m);
    if (lane < FV) {
        float4 hv = *(const float4*)(h + (size_t)n * F + lane * 4);
        acc.x += es * hv.x; acc.y += es * hv.y;
        acc.z += es * hv.z; acc.w += es * hv.w;
    }
    if (lane == 0) Sp += es;
    #pragma unroll
    for (int o = 16; o; o >>= 1) Sp += __shfl_xor_sync(FULL, Sp, o);

    float inv = 1.f / (Sp + 1e-16f);
    float4 o4 = make_float4(0.f, 0.f, 0.f, 0.f);
    if (lane < FV) {
        float4 bb = *(const float4*)(bias + lane * 4);
        o4.x = fmaxf(acc.x * inv + bb.x, 0.f);
        o4.y = fmaxf(acc.y * inv + bb.y, 0.f);
        o4.z = fmaxf(acc.z * inv + bb.z, 0.f);
        o4.w = fmaxf(acc.w * inv + bb.w, 0.f);
    }

    if (LAYER == 1) {
        // fused gemm2: h2[n, :] = out1[n, :] @ W2  (48x60), out1 lives in lanes 0..11
        int c0 = lane, c1 = lane + 32;
        float h2a = 0.f, h2b = 0.f;
        #pragma unroll
        for (int kk = 0; kk < 12; kk++) {
            float b0 = __shfl_sync(FULL, o4.x, kk);
            float b1 = __shfl_sync(FULL, o4.y, kk);
            float b2 = __shfl_sync(FULL, o4.z, kk);
            float b3 = __shfl_sync(FULL, o4.w, kk);
            float4 w0 = *(const float4*)&sW2t[c0][kk * 4];
            h2a += b0 * w0.x + b1 * w0.y + b2 * w0.z + b3 * w0.w;
            if (c1 < 60) {
                float4 w1 = *(const float4*)&sW2t[c1][kk * 4];
                h2b += b0 * w1.x + b1 * w1.y + b2 * w1.z + b3 * w1.w;
            }
        }
        g_h2[(size_t)n * 60 + c0] = h2a;
        if (c1 < 60) g_h2[(size_t)n * 60 + c1] = h2b;
        float ps = h2a * sAs[c0] + (c1 < 60 ? h2b * sAs[c1] : 0.f);
        float pd = h2a * sAd[c0] + (c1 < 60 ? h2b * sAd[c1] : 0.f);
        #pragma unroll
        for (int o = 16; o; o >>= 1) {
            ps += __shfl_xor_sync(FULL, ps, o);
            pd += __shfl_xor_sync(FULL, pd, o);
        }
        if (lane == 0) { g_asB[n] = ps; g_adB[n] = pd; }
    } else {
        // fused layer-3 projection: h3 = out2 @ W3 (60x1) + alphas
        float d = 0.f;
        if (lane < FV) {
            float4 w = *(const float4*)(Wnext + lane * 4);
            d = o4.x * w.x + o4.y * w.y + o4.z * w.z + o4.w * w.w;
        }
        #pragma unroll
        for (int o = 16; o; o >>= 1) d += __shfl_xor_sync(FULL, d, o);
        if (lane == 0) {
            g_h3[n] = d;
            g_as[n] = d * asn[0];
            g_ad[n] = d * adn_v[0];
        }
    }
}

// ---------------- layer 3 aggregation (scalar feature) ----------------
__global__ __launch_bounds__(256) void agg3_k(const float* __restrict__ b3,
                                              float* __restrict__ out, int N) {
    int n = (blockIdx.x * blockDim.x + threadIdx.x) >> 5;
    int lane = threadIdx.x & 31;
    if (n >= N) return;
    int beg = g_ro[n], end = g_ro[n + 1];
    float adn = g_ad[n];
    float lself = lrelu(g_as[n] + adn);
    float m = lself;
    for (int j = beg + lane; j < end; j += 32) {
        float l = lrelu(g_as[g_csrc[j]] + adn);
        g_elog[j] = l;
        m = fmaxf(m, l);
    }
    #pragma unroll
    for (int o = 16; o; o >>= 1) m = fmaxf(m, __shfl_xor_sync(FULL, m, o));
    float S = 0.f, A = 0.f;
    for (int j = beg + lane; j < end; j += 32) {
        int s = g_csrc[j];
        float e = __expf(g_elog[j] - m);
        S += e;
        A += e * g_h3[s];
    }
    if (lane == 0) {
        float es = __expf(lself - m);
        S += es;
        A += es * g_h3[n];
    }
    #pragma unroll
    for (int o = 16; o; o >>= 1) {
        S += __shfl_xor_sync(FULL, S, o);
        A += __shfl_xor_sync(FULL, A, o);
    }
    if (lane == 0) out[n] = A / (S + 1e-16f) + b3[0];
}

// ---------------- launch ----------------
extern "C" void kernel_launch(void* const* d_in, const int* in_sizes, int n_in,
                              void* d_out, int out_size) {
    const float* x   = (const float*)d_in[0];
    const void*  ei  = d_in[1];
    // d_in[2] = edge_attr (ignored by the reference model)
    const float* W1  = (const float*)d_in[3];
    const float* as1 = (const float*)d_in[4];
    const float* ad1 = (const float*)d_in[5];
    const float* b1  = (const float*)d_in[6];
    const float* W2  = (const float*)d_in[7];
    const float* as2 = (const float*)d_in[8];
    const float* ad2 = (const float*)d_in[9];
    const float* b2  = (const float*)d_in[10];
    const float* W3  = (const float*)d_in[11];
    const float* as3 = (const float*)d_in[12];
    const float* ad3 = (const float*)d_in[13];
    const float* b3  = (const float*)d_in[14];

    int N = out_size;            // output is [N] floats
    int E = in_sizes[1] / 2;     // edge_index is [2, E]

    int blocksE = (E + 255) / 256;
    int wb = (N + 7) / 8;        // warp-per-node, 8 warps/block
    int gb = (N + 63) / 64;      // gemm row tiles
    int nb = (N + 1023) / 1024;  // scan blocks

    // one-time side-stream infrastructure (created on first, uncaptured, call)
    static cudaStream_t s2 = nullptr;
    static cudaEvent_t evFork = nullptr, evJoin = nullptr;
    if (s2 == nullptr) {
        cudaStreamCreateWithFlags(&s2, cudaStreamNonBlocking);
        cudaEventCreateWithFlags(&evFork, cudaEventDisableTiming);
        cudaEventCreateWithFlags(&evJoin, cudaEventDisableTiming);
    }

    // fork: CSR build on s2, GEMM1 on the main (captured) stream
    cudaEventRecord(evFork, 0);
    cudaStreamWaitEvent(s2, evFork, 0);

    zero_k<<<(N + 1023) / 1024, 1024, 0, s2>>>(N);
    detect_k<<<1, 32, 0, s2>>>(ei);
    hist_k<<<blocksE, 256, 0, s2>>>(ei, E);
    scanA_k<<<nb, 256, 0, s2>>>(N);
    scanB_k<<<1, 64, 0, s2>>>(nb, N);
    scanC_k<<<nb, 256, 0, s2>>>(N);
    scat_k<<<blocksE, 256, 0, s2>>>(ei, E);
    cudaEventRecord(evJoin, s2);

    gemm1_k<<<gb, 256>>>(x, W1, as1, ad1, N);

    // join: everything after needs both CSR and h1/alpha1
    cudaStreamWaitEvent(0, evJoin, 0);

    agg_k<1><<<wb, 256>>>(b1, W2, as2, ad2, N);
    agg_k<2><<<wb, 256>>>(b2, W3, as3, ad3, N);
    agg3_k<<<wb, 256>>>(b3, (float*)d_out, N);
}

// round 6
// speedup vs baseline: 1.1725x; 1.1725x over previous
#include <cuda_runtime.h>
#include <cstdint>
#include <math.h>

#define NMAX 50176
#define EMAX 1700000
#define NEG 0.2f
#define FULL 0xffffffffu

// ---------------- device scratch (static; no allocation) ----------------
__device__ float g_h1[(size_t)NMAX * 48];
__device__ float g_out1[(size_t)NMAX * 48];
__device__ float g_h2[(size_t)NMAX * 60];
__device__ float2 g_p3[NMAX];   // (as3*d, d) packed for layer-3 gather
__device__ float g_as[NMAX];    // alphas of current layer (1 then 2)
__device__ float g_ad[NMAX];
__device__ float g_adB[NMAX];   // layer-3 ad
__device__ int   g_cnt[NMAX + 1];
__device__ int   g_ro[NMAX + 1];
__device__ int   g_nxt[NMAX];
__device__ int   g_csrc[EMAX];
__device__ int   g_bsum[64];
__device__ int   g_boff[64];
__device__ int   g_is64;
__device__ unsigned g_mx1, g_mx2, g_mx3;  // encoded global max of as per layer

__device__ __forceinline__ float lrelu(float x) { return x > 0.f ? x : NEG * x; }

// monotone float <-> uint encoding for atomicMax over signed floats
__device__ __forceinline__ unsigned fenc(float f) {
    unsigned u = __float_as_uint(f);
    return (u & 0x80000000u) ? ~u : (u | 0x80000000u);
}
__device__ __forceinline__ float fdec(unsigned u) {
    return (u & 0x80000000u) ? __uint_as_float(u & 0x7fffffffu) : __uint_as_float(~u);
}

__global__ void init_k() { g_mx1 = 0u; g_mx2 = 0u; g_mx3 = 0u; }

// ---------------- edge-index dtype detection ----------------
__global__ void detect_k(const void* ei) {
    int lane = threadIdx.x;
    const int* p = (const int*)ei;
    int v = p[2 * lane + 1];
    unsigned b = __ballot_sync(FULL, v == 0);
    if (lane == 0) g_is64 = (b == FULL) ? 1 : 0;
}

__device__ __forceinline__ int edge_val(const void* ei, int idx) {
    if (g_is64) return (int)((const long long*)ei)[idx];
    return ((const int*)ei)[idx];
}

// ---------------- CSR build ----------------
__global__ void zero_k(int n) {
    int i = blockIdx.x * blockDim.x + threadIdx.x;
    if (i < n) g_cnt[i] = 0;
}

__global__ void hist_k(const void* ei, int E) {
    int e = blockIdx.x * blockDim.x + threadIdx.x;
    if (e < E) {
        int d = edge_val(ei, E + e);
        atomicAdd(&g_cnt[d], 1);
    }
}

// multi-block exclusive scan of g_cnt[0..N) -> g_ro ; 1024 elems/block
__global__ __launch_bounds__(256) void scanA_k(int N) {
    __shared__ int wsum[8];
    int tid = threadIdx.x, lane = tid & 31, wid = tid >> 5;
    int base = blockIdx.x * 1024 + tid * 4;
    int v[4];
    #pragma unroll
    for (int k = 0; k < 4; k++) v[k] = (base + k < N) ? g_cnt[base + k] : 0;
    int s4 = v[0] + v[1] + v[2] + v[3];
    int x = s4;
    #pragma unroll
    for (int o = 1; o < 32; o <<= 1) {
        int t = __shfl_up_sync(FULL, x, o);
        if (lane >= o) x += t;
    }
    if (lane == 31) wsum[wid] = x;
    __syncthreads();
    if (wid == 0 && lane < 8) {
        int w = wsum[lane];
        #pragma unroll
        for (int o = 1; o < 8; o <<= 1) {
            int t = __shfl_up_sync(0xffu, w, o);
            if (lane >= o) w += t;
        }
        wsum[lane] = w;
    }
    __syncthreads();
    int excl = (wid ? wsum[wid - 1] : 0) + x - s4;
    int run = excl;
    #pragma unroll
    for (int k = 0; k < 4; k++) {
        if (base + k < N) g_ro[base + k] = run;
        run += v[k];
    }
    if (tid == 255) g_bsum[blockIdx.x] = wsum[7];
}

__global__ void scanB_k(int nb, int N) {
    int tid = threadIdx.x;  // 64 threads
    int lane = tid & 31, wid = tid >> 5;
    __shared__ int w0tot;
    int v = (tid < nb) ? g_bsum[tid] : 0;
    int x = v;
    #pragma unroll
    for (int o = 1; o < 32; o <<= 1) {
        int t = __shfl_up_sync(FULL, x, o);
        if (lane >= o) x += t;
    }
    if (wid == 0 && lane == 31) w0tot = x;
    __syncthreads();
    if (wid == 1) x += w0tot;
    g_boff[tid] = x - v;
    if (tid == 63) g_ro[N] = x;
}

__global__ __launch_bounds__(256) void scanC_k(int N) {
    int base = blockIdx.x * 1024 + threadIdx.x * 4;
    int off = g_boff[blockIdx.x];
    #pragma unroll
    for (int k = 0; k < 4; k++) {
        int i = base + k;
        if (i < N) {
            int r = g_ro[i] + off;
            g_ro[i] = r;
            g_nxt[i] = r;
        }
    }
}

__global__ void scat_k(const void* ei, int E) {
    int e = blockIdx.x * blockDim.x + threadIdx.x;
    if (e < E) {
        int s = edge_val(ei, e);
        int d = edge_val(ei, E + e);
        int p = atomicAdd(&g_nxt[d], 1);
        g_csrc[p] = s;
    }
}

// ---------------- GEMM layer 1: [N,256] x [256,48] -> g_h1 ; fused alpha + maxAS ----------------
__global__ __launch_bounds__(256) void gemm1_k(const float* __restrict__ X,
                                               const float* __restrict__ W,
                                               const float* __restrict__ av_s,
                                               const float* __restrict__ av_d, int N) {
    __shared__ float sX[64][68];
    __shared__ float sW[64][48];
    __shared__ float sWm[8];
    int tid = threadIdx.x;
    int tx = tid & 15, ty = tid >> 4;
    int lane = tid & 31, wid = tid >> 5;
    int row0 = blockIdx.x * 64;
    float acc[4][3];
    #pragma unroll
    for (int i = 0; i < 4; i++)
        #pragma unroll
        for (int j = 0; j < 3; j++) acc[i][j] = 0.f;

    for (int k0 = 0; k0 < 256; k0 += 64) {
        for (int i = tid; i < 64 * 16; i += 256) {
            int r = i >> 4; int kq = (i & 15) * 4;
            int gr = row0 + r;
            float4 v = (gr < N) ? *(const float4*)&X[(size_t)gr * 256 + k0 + kq]
                                : make_float4(0.f, 0.f, 0.f, 0.f);
            *(float4*)&sX[r][kq] = v;
        }
        for (int i = tid; i < 64 * 12; i += 256) {
            int r = i / 12; int cq = (i % 12) * 4;
            float4 v = *(const float4*)&W[(size_t)(k0 + r) * 48 + cq];
            *(float4*)&sW[r][cq] = v;
        }
        __syncthreads();
        #pragma unroll 16
        for (int k = 0; k < 64; k++) {
            float a0 = sX[ty * 4 + 0][k], a1 = sX[ty * 4 + 1][k];
            float a2 = sX[ty * 4 + 2][k], a3 = sX[ty * 4 + 3][k];
            float w0 = sW[k][tx * 3 + 0], w1 = sW[k][tx * 3 + 1], w2 = sW[k][tx * 3 + 2];
            acc[0][0] += a0 * w0; acc[0][1] += a0 * w1; acc[0][2] += a0 * w2;
            acc[1][0] += a1 * w0; acc[1][1] += a1 * w1; acc[1][2] += a1 * w2;
            acc[2][0] += a2 * w0; acc[2][1] += a2 * w1; acc[2][2] += a2 * w2;
            acc[3][0] += a3 * w0; acc[3][1] += a3 * w1; acc[3][2] += a3 * w2;
        }
        __syncthreads();
    }
    #pragma unroll
    for (int i = 0; i < 4; i++) {
        int gr = row0 + ty * 4 + i;
        if (gr < N) {
            #pragma unroll
            for (int j = 0; j < 3; j++)
                g_h1[(size_t)gr * 48 + tx * 3 + j] = acc[i][j];
        }
    }
    // fused alpha: reduce over 16 threads of the same row group
    float a_s[3], a_d[3];
    #pragma unroll
    for (int j = 0; j < 3; j++) { a_s[j] = av_s[tx * 3 + j]; a_d[j] = av_d[tx * 3 + j]; }
    float pmax = -INFINITY;
    #pragma unroll
    for (int i = 0; i < 4; i++) {
        float ps = acc[i][0] * a_s[0] + acc[i][1] * a_s[1] + acc[i][2] * a_s[2];
        float pd = acc[i][0] * a_d[0] + acc[i][1] * a_d[1] + acc[i][2] * a_d[2];
        #pragma unroll
        for (int o = 8; o; o >>= 1) {
            ps += __shfl_down_sync(FULL, ps, o, 16);
            pd += __shfl_down_sync(FULL, pd, o, 16);
        }
        if (tx == 0) {
            int gr = row0 + ty * 4 + i;
            if (gr < N) { g_as[gr] = ps; g_ad[gr] = pd; pmax = fmaxf(pmax, ps); }
        }
    }
    // block max of as -> g_mx1
    pmax = fmaxf(pmax, __shfl_xor_sync(FULL, pmax, 16));
    if (lane == 0) sWm[wid] = pmax;
    __syncthreads();
    if (wid == 0) {
        float v = (lane < 8) ? sWm[lane] : -INFINITY;
        #pragma unroll
        for (int o = 4; o; o >>= 1) v = fmaxf(v, __shfl_down_sync(FULL, v, o));
        if (lane == 0) atomicMax(&g_mx1, fenc(v));
    }
}

// ---------------- GEMM layer 2: g_out1 [N,48] x [48,60] -> g_h2 ; fused alpha + maxAS ----------------
__global__ __launch_bounds__(256) void gemm2_k(const float* __restrict__ W,
                                               const float* __restrict__ av_s,
                                               const float* __restrict__ av_d, int N) {
    __shared__ float sX[64][52];
    __shared__ float sW[48][64];
    __shared__ float sWm[8];
    int tid = threadIdx.x;
    int tx = tid & 15, ty = tid >> 4;
    int lane = tid & 31, wid = tid >> 5;
    int row0 = blockIdx.x * 64;

    for (int i = tid; i < 768; i += 256) {
        int r = i / 12; int kq = (i % 12) * 4;
        int gr = row0 + r;
        float4 v = (gr < N) ? *(const float4*)&g_out1[(size_t)gr * 48 + kq]
                            : make_float4(0.f, 0.f, 0.f, 0.f);
        *(float4*)&sX[r][kq] = v;
    }
    for (int i = tid; i < 720; i += 256) {
        int r = i / 15; int cq = (i % 15) * 4;
        float4 v = *(const float4*)&W[(size_t)r * 60 + cq];
        *(float4*)&sW[r][cq] = v;
    }
    __syncthreads();

    float acc[4][4];
    #pragma unroll
    for (int i = 0; i < 4; i++)
        #pragma unroll
        for (int j = 0; j < 4; j++) acc[i][j] = 0.f;

    #pragma unroll 12
    for (int k = 0; k < 48; k++) {
        float a0 = sX[ty * 4 + 0][k], a1 = sX[ty * 4 + 1][k];
        float a2 = sX[ty * 4 + 2][k], a3 = sX[ty * 4 + 3][k];
        float4 w = *(const float4*)&sW[k][tx * 4];
        acc[0][0] += a0 * w.x; acc[0][1] += a0 * w.y; acc[0][2] += a0 * w.z; acc[0][3] += a0 * w.w;
        acc[1][0] += a1 * w.x; acc[1][1] += a1 * w.y; acc[1][2] += a1 * w.z; acc[1][3] += a1 * w.w;
        acc[2][0] += a2 * w.x; acc[2][1] += a2 * w.y; acc[2][2] += a2 * w.z; acc[2][3] += a2 * w.w;
        acc[3][0] += a3 * w.x; acc[3][1] += a3 * w.y; acc[3][2] += a3 * w.z; acc[3][3] += a3 * w.w;
    }
    #pragma unroll
    for (int i = 0; i < 4; i++) {
        int gr = row0 + ty * 4 + i;
        if (gr < N) {
            #pragma unroll
            for (int j = 0; j < 4; j++) {
                int c = tx * 4 + j;
                if (c < 60) g_h2[(size_t)gr * 60 + c] = acc[i][j];
            }
        }
    }
    // fused alpha (cols >= 60 masked out)
    float a_s[4], a_d[4];
    #pragma unroll
    for (int j = 0; j < 4; j++) {
        int c = tx * 4 + j;
        a_s[j] = (c < 60) ? av_s[c] : 0.f;
        a_d[j] = (c < 60) ? av_d[c] : 0.f;
    }
    float pmax = -INFINITY;
    #pragma unroll
    for (int i = 0; i < 4; i++) {
        float ps = acc[i][0] * a_s[0] + acc[i][1] * a_s[1] + acc[i][2] * a_s[2] + acc[i][3] * a_s[3];
        float pd = acc[i][0] * a_d[0] + acc[i][1] * a_d[1] + acc[i][2] * a_d[2] + acc[i][3] * a_d[3];
        #pragma unroll
        for (int o = 8; o; o >>= 1) {
            ps += __shfl_down_sync(FULL, ps, o, 16);
            pd += __shfl_down_sync(FULL, pd, o, 16);
        }
        if (tx == 0) {
            int gr = row0 + ty * 4 + i;
            if (gr < N) { g_as[gr] = ps; g_ad[gr] = pd; pmax = fmaxf(pmax, ps); }
        }
    }
    pmax = fmaxf(pmax, __shfl_xor_sync(FULL, pmax, 16));
    if (lane == 0) sWm[wid] = pmax;
    __syncthreads();
    if (wid == 0) {
        float v = (lane < 8) ? sWm[lane] : -INFINITY;
        #pragma unroll
        for (int o = 4; o; o >>= 1) v = fmaxf(v, __shfl_down_sync(FULL, v, o));
        if (lane == 0) atomicMax(&g_mx2, fenc(v));
    }
}

// ---------------- fused segment softmax + aggregation (warp per node, single pass) ----------------
// Stabilizer m = lrelu(maxAS + ad[n]) is a segment upper bound (lrelu monotone),
// so the per-node max gather pass is unnecessary (softmax is shift-invariant).
// LAYER==1: reads g_h1; writes g_out1.
// LAYER==2: reads g_h2; epilogue computes h3 = out2 @ W3, packs (as3*h3, h3) into
//           g_p3, writes g_adB, and accumulates max(as3*h3) into g_mx3.
template <int LAYER>
__global__ __launch_bounds__(256) void agg_k(const float* __restrict__ bias,
                                             const float* __restrict__ W3,
                                             const float* __restrict__ as3,
                                             const float* __restrict__ ad3, int N) {
    constexpr int F = (LAYER == 1) ? 48 : 60;
    constexpr int FV = F / 4;
    const float* h = (LAYER == 1) ? g_h1 : g_h2;
    __shared__ float sWm[8];

    int tid = threadIdx.x;
    int n = (blockIdx.x * blockDim.x + tid) >> 5;
    int lane = tid & 31, wid = tid >> 5;
    bool valid = n < N;

    float maxAS = fdec((LAYER == 1) ? g_mx1 : g_mx2);
    int beg = 0, end = 0;
    float adn = 0.f, lself = 0.f, m = 0.f;
    if (valid) {
        beg = g_ro[n]; end = g_ro[n + 1];
        adn = g_ad[n];
        lself = lrelu(g_as[n] + adn);
        m = lrelu(maxAS + adn);
    }

    int half = lane >> 4;
    int hl = lane & 15;
    const bool act = hl < FV;
    float4 acc = make_float4(0.f, 0.f, 0.f, 0.f);
    float Sp = 0.f;
    for (int j0 = beg; j0 < end; j0 += 32) {
        int j = j0 + lane;
        int s = 0; float e = 0.f;
        if (j < end) {
            s = g_csrc[j];
            e = __expf(lrelu(g_as[s] + adn) - m);
            Sp += e;
        }
        int cnt = min(32, end - j0);
        for (int jj = 0; jj < cnt; jj += 2) {
            int idx = jj + half;
            float ee = __shfl_sync(FULL, e, idx);
            int ss = __shfl_sync(FULL, s, idx);
            if (act && idx < cnt) {
                float4 hv = *(const float4*)(h + (size_t)ss * F + hl * 4);
                acc.x += ee * hv.x; acc.y += ee * hv.y;
                acc.z += ee * hv.z; acc.w += ee * hv.w;
            }
        }
    }
    // combine halves
    acc.x += __shfl_down_sync(FULL, acc.x, 16);
    acc.y += __shfl_down_sync(FULL, acc.y, 16);
    acc.z += __shfl_down_sync(FULL, acc.z, 16);
    acc.w += __shfl_down_sync(FULL, acc.w, 16);

    float es = __expf(lself - m);
    if (valid && lane < FV) {
        float4 hv = *(const float4*)(h + (size_t)n * F + lane * 4);
        acc.x += es * hv.x; acc.y += es * hv.y;
        acc.z += es * hv.z; acc.w += es * hv.w;
    }
    if (lane == 0) Sp += es;
    #pragma unroll
    for (int o = 16; o; o >>= 1) Sp += __shfl_xor_sync(FULL, Sp, o);

    float inv = 1.f / (Sp + 1e-16f);
    float4 o4 = make_float4(0.f, 0.f, 0.f, 0.f);
    if (lane < FV) {
        float4 bb = *(const float4*)(bias + lane * 4);
        o4.x = fmaxf(acc.x * inv + bb.x, 0.f);
        o4.y = fmaxf(acc.y * inv + bb.y, 0.f);
        o4.z = fmaxf(acc.z * inv + bb.z, 0.f);
        o4.w = fmaxf(acc.w * inv + bb.w, 0.f);
        if (LAYER == 1 && valid) *(float4*)(g_out1 + (size_t)n * F + lane * 4) = o4;
    }
    if (LAYER == 2) {
        // fused layer-3 projection + alphas + maxAS3
        float d = 0.f;
        if (lane < FV) {
            float4 w = *(const float4*)(W3 + lane * 4);
            d = o4.x * w.x + o4.y * w.y + o4.z * w.z + o4.w * w.w;
        }
        #pragma unroll
        for (int o = 16; o; o >>= 1) d += __shfl_xor_sync(FULL, d, o);
        float pm = -INFINITY;
        if (valid && lane == 0) {
            float a = d * as3[0];
            g_p3[n] = make_float2(a, d);
            g_adB[n] = d * ad3[0];
            pm = a;
        }
        if (lane == 0) sWm[wid] = pm;
        __syncthreads();
        if (wid == 0) {
            float v = (lane < 8) ? sWm[lane] : -INFINITY;
            #pragma unroll
            for (int o = 4; o; o >>= 1) v = fmaxf(v, __shfl_down_sync(FULL, v, o));
            if (lane == 0) atomicMax(&g_mx3, fenc(v));
        }
    }
}

// ---------------- layer 3 aggregation (scalar feature, single pass) ----------------
__global__ __launch_bounds__(256) void agg3_k(const float* __restrict__ b3,
                                              float* __restrict__ out, int N) {
    int n = (blockIdx.x * blockDim.x + threadIdx.x) >> 5;
    int lane = threadIdx.x & 31;
    if (n >= N) return;
    int beg = g_ro[n], end = g_ro[n + 1];
    float adn = g_adB[n];
    float2 pn = g_p3[n];
    float lself = lrelu(pn.x + adn);
    float m = lrelu(fdec(g_mx3) + adn);
    float S = 0.f, A = 0.f;
    for (int j = beg + lane; j < end; j += 32) {
        int s = g_csrc[j];
        float2 p = g_p3[s];
        float e = __expf(lrelu(p.x + adn) - m);
        S += e;
        A += e * p.y;
    }
    if (lane == 0) {
        float es = __expf(lself - m);
        S += es;
        A += es * pn.y;
    }
    #pragma unroll
    for (int o = 16; o; o >>= 1) {
        S += __shfl_xor_sync(FULL, S, o);
        A += __shfl_xor_sync(FULL, A, o);
    }
    if (lane == 0) out[n] = A / (S + 1e-16f) + b3[0];
}

// ---------------- launch ----------------
extern "C" void kernel_launch(void* const* d_in, const int* in_sizes, int n_in,
                              void* d_out, int out_size) {
    const float* x   = (const float*)d_in[0];
    const void*  ei  = d_in[1];
    // d_in[2] = edge_attr (ignored by the reference model)
    const float* W1  = (const float*)d_in[3];
    const float* as1 = (const float*)d_in[4];
    const float* ad1 = (const float*)d_in[5];
    const float* b1  = (const float*)d_in[6];
    const float* W2  = (const float*)d_in[7];
    const float* as2 = (const float*)d_in[8];
    const float* ad2 = (const float*)d_in[9];
    const float* b2  = (const float*)d_in[10];
    const float* W3  = (const float*)d_in[11];
    const float* as3 = (const float*)d_in[12];
    const float* ad3 = (const float*)d_in[13];
    const float* b3  = (const float*)d_in[14];

    int N = out_size;            // output is [N] floats
    int E = in_sizes[1] / 2;     // edge_index is [2, E]

    int blocksE = (E + 255) / 256;
    int wb = (N + 7) / 8;        // warp-per-node, 8 warps/block
    int gb = (N + 63) / 64;      // gemm row tiles
    int nb = (N + 1023) / 1024;  // scan blocks

    // one-time side-stream infrastructure (created on first, uncaptured, call)
    static cudaStream_t s2 = nullptr;
    static cudaEvent_t evFork = nullptr, evJoin = nullptr;
    if (s2 == nullptr) {
        cudaStreamCreateWithFlags(&s2, cudaStreamNonBlocking);
        cudaEventCreateWithFlags(&evFork, cudaEventDisableTiming);
        cudaEventCreateWithFlags(&evJoin, cudaEventDisableTiming);
    }

    init_k<<<1, 1>>>();

    // fork: CSR build on s2, GEMM1 on the main (captured) stream
    cudaEventRecord(evFork, 0);
    cudaStreamWaitEvent(s2, evFork, 0);

    zero_k<<<(N + 1023) / 1024, 1024, 0, s2>>>(N);
    detect_k<<<1, 32, 0, s2>>>(ei);
    hist_k<<<blocksE, 256, 0, s2>>>(ei, E);
    scanA_k<<<nb, 256, 0, s2>>>(N);
    scanB_k<<<1, 64, 0, s2>>>(nb, N);
    scanC_k<<<nb, 256, 0, s2>>>(N);
    scat_k<<<blocksE, 256, 0, s2>>>(ei, E);
    cudaEventRecord(evJoin, s2);

    gemm1_k<<<gb, 256>>>(x, W1, as1, ad1, N);

    // join: everything after needs both CSR and h1/alpha1
    cudaStreamWaitEvent(0, evJoin, 0);

    agg_k<1><<<wb, 256>>>(b1, nullptr, nullptr, nullptr, N);
    gemm2_k<<<gb, 256>>>(W2, as2, ad2, N);
    agg_k<2><<<wb, 256>>>(b2, W3, as3, ad3, N);
    agg3_k<<<wb, 256>>>(b3, (float*)d_out, N);
}